// round 6
// baseline (speedup 1.0000x reference)
#include <cuda_runtime.h>
#include <cuda_bf16.h>
#include <cstdint>

#define B_ROWS 8192
#define DIM    128
#define BM     128
#define SH     136            // halves per smem bf16 row (272 B): LDSM conflict-free
#define CW     132            // floats per smem score row (16B-aligned rows)
#define NTILES 2080           // 64*65/2 upper-triangle tiles
#define NEG_INF_F (-1e30f)
#define POS_INF_F ( 1e30f)
#define MARGIN_F  0.2f

// ---------------- device-global state ----------------
__device__ unsigned       g_max_enc[B_ROWS];
__device__ unsigned       g_min_enc[B_ROWS];
__device__ __nv_bfloat16  g_im_bf16[B_ROWS * DIM];   // 2 MB, L2-resident
__device__ int            g_ids32[B_ROWS];

__device__ __forceinline__ unsigned enc_f(float f) {
    unsigned u = __float_as_uint(f);
    return (u & 0x80000000u) ? ~u : (u | 0x80000000u);
}
__device__ __forceinline__ float dec_f(unsigned u) {
    return __uint_as_float((u & 0x80000000u) ? (u & 0x7FFFFFFFu) : ~u);
}
__device__ __forceinline__ uint32_t smem_u32(const void* p) {
    uint32_t a;
    asm("{ .reg .u64 t; cvta.to.shared.u64 t, %1; cvt.u32.u64 %0, t; }" : "=r"(a) : "l"(p));
    return a;
}
#define LDSM_X4(r0, r1, r2, r3, addr) \
    asm volatile("ldmatrix.sync.aligned.m8n8.x4.shared.b16 {%0,%1,%2,%3}, [%4];" \
                 : "=r"(r0), "=r"(r1), "=r"(r2), "=r"(r3) : "r"(addr))

// ---------------------------------------------------------------------------
// Kernel 1: convert im -> bf16 (persistent), ids -> int32, clear reductions.
// 262144 threads, 4 floats each (higher MLP than R5's 8-float version).
// ---------------------------------------------------------------------------
__global__ void convert_kernel(const float* __restrict__ im, const void* __restrict__ ids) {
    __shared__ int s_is64;
    const int tid = blockIdx.x * blockDim.x + threadIdx.x;   // 1024*256

    if (blockIdx.x < 32) {   // these blocks also handle ids + reduction arrays
        if (threadIdx.x < 32) {
            const unsigned* w = (const unsigned*)ids;
            unsigned v = w[2 * threadIdx.x + 1] | w[2 * threadIdx.x + 65];
            unsigned any = __ballot_sync(0xffffffffu, v != 0u);
            if (threadIdx.x == 0) s_is64 = (any == 0u) ? 1 : 0;
        }
        __syncthreads();
        g_max_enc[tid] = enc_f(NEG_INF_F);
        g_min_enc[tid] = enc_f(POS_INF_F);
        g_ids32[tid] = s_is64 ? (int)((const long long*)ids)[tid]
                              : ((const int*)ids)[tid];
    }
    float4 v = ((const float4*)im)[tid];
    __nv_bfloat162* dst = (__nv_bfloat162*)g_im_bf16 + (size_t)tid * 2;
    dst[0] = __floats2bfloat162_rn(v.x, v.y);
    dst[1] = __floats2bfloat162_rn(v.z, v.w);
}

// ---------------------------------------------------------------------------
// Kernel 2: symmetric bf16 mma.sync tile + smem-transpose epilogue.
// Linear triangular grid (2080 blocks). Block = 256 thr = 8 warps (4m x 2n),
// warp tile 32x64, mma m16n8k16, fragments via ldmatrix.x4.
// Epilogue: acc -> smem fp32 [128][CW]; threads 0..127 reduce rows (anchors
// m0+r) and threads 128..255 reduce cols (anchors n0+c, off-diag only),
// both with 4 independent min/max chains + int4-vectorized id loads.
// ---------------------------------------------------------------------------
__global__ void __launch_bounds__(256, 2)
tile_kernel(void) {
    // closed-form linear -> (bi, bj) with bj >= bi:
    // start(bi) = bi*(129-bi)/2 ; bi = largest with start(bi) <= k
    const int k = blockIdx.x;
    int bi = (int)(64.5 - sqrt(64.5 * 64.5 - 2.0 * (double)k));
    while (bi > 0 && bi * (129 - bi) / 2 > k) --bi;
    while ((bi + 1) * (128 - bi) / 2 <= k) ++bi;
    const int bj = bi + (k - bi * (129 - bi) / 2);
    const bool diag = (bi == bj);
    const int m0 = bi * BM, n0 = bj * BM;

    extern __shared__ char smem[];
    unsigned short* As = (unsigned short*)smem;          // [BM][SH]
    unsigned short* Bs = As + BM * SH;                   // [BM][SH]
    float*          Cs = (float*)smem;                   // [BM][CW], aliases A/B
    __shared__ alignas(16) int s_idr[BM], s_idc[BM];

    const int tid = threadIdx.x;
    if (tid < BM) {
        s_idr[tid] = g_ids32[m0 + tid];
        s_idc[tid] = g_ids32[n0 + tid];
    }

    // Stage bf16 tiles: 2048 x 16B each, STS.128 conflict-free.
#pragma unroll
    for (int it = 0; it < 8; ++it) {
        int idx = it * 256 + tid;
        int row = idx >> 4, q = idx & 15;        // q: 16B chunk in 256B row
        *(uint4*)(As + row * SH + q * 8) =
            *(const uint4*)(g_im_bf16 + (size_t)(m0 + row) * DIM + q * 8);
        *(uint4*)(Bs + row * SH + q * 8) =
            *(const uint4*)(g_im_bf16 + (size_t)(n0 + row) * DIM + q * 8);
    }
    __syncthreads();

    const int warp = tid >> 5, lane = tid & 31;
    const int wm = warp >> 1, wn = warp & 1;     // warp tile origin (wm*32, wn*64)
    const int g = lane >> 2, tig = lane & 3;
    const int grp = lane >> 3, rin = lane & 7;

    const uint32_t As32 = smem_u32(As), Bs32 = smem_u32(Bs);
    uint32_t aaddr[2], baddr[4];
#pragma unroll
    for (int mt = 0; mt < 2; ++mt)
        aaddr[mt] = As32 + 2 * ((wm * 32 + mt * 16 + (grp & 1) * 8 + rin) * SH + (grp >> 1) * 8);
#pragma unroll
    for (int q = 0; q < 4; ++q)
        baddr[q] = Bs32 + 2 * ((wn * 64 + 16 * q + (grp >> 1) * 8 + rin) * SH + (grp & 1) * 8);

    float acc[2][8][4];
#pragma unroll
    for (int mt = 0; mt < 2; ++mt)
#pragma unroll
        for (int nt = 0; nt < 8; ++nt)
#pragma unroll
            for (int r = 0; r < 4; ++r) acc[mt][nt][r] = 0.0f;

#pragma unroll
    for (int ks = 0; ks < 8; ++ks) {
        const uint32_t koff = ks * 32;           // 16 halves = 32 bytes
        unsigned a[2][4], b[8][2];
#pragma unroll
        for (int mt = 0; mt < 2; ++mt)
            LDSM_X4(a[mt][0], a[mt][1], a[mt][2], a[mt][3], aaddr[mt] + koff);
#pragma unroll
        for (int q = 0; q < 4; ++q)
            LDSM_X4(b[2 * q][0], b[2 * q][1], b[2 * q + 1][0], b[2 * q + 1][1], baddr[q] + koff);
#pragma unroll
        for (int mt = 0; mt < 2; ++mt)
#pragma unroll
            for (int nt = 0; nt < 8; ++nt) {
                asm volatile(
                    "mma.sync.aligned.m16n8k16.row.col.f32.bf16.bf16.f32 "
                    "{%0,%1,%2,%3}, {%4,%5,%6,%7}, {%8,%9}, {%0,%1,%2,%3};"
                    : "+f"(acc[mt][nt][0]), "+f"(acc[mt][nt][1]),
                      "+f"(acc[mt][nt][2]), "+f"(acc[mt][nt][3])
                    : "r"(a[mt][0]), "r"(a[mt][1]), "r"(a[mt][2]), "r"(a[mt][3]),
                      "r"(b[nt][0]), "r"(b[nt][1]));
            }
    }
    __syncthreads();   // done reading As/Bs; Cs may overwrite

    // Scatter acc to Cs: row = wm*32+mt*16+g+half*8, cols wn*64+nt*8+2*tig+{0,1}
#pragma unroll
    for (int mt = 0; mt < 2; ++mt)
#pragma unroll
        for (int half = 0; half < 2; ++half) {
            const int lr = wm * 32 + mt * 16 + g + half * 8;
#pragma unroll
            for (int nt = 0; nt < 8; ++nt) {
                float2 v = make_float2(acc[mt][nt][half * 2], acc[mt][nt][half * 2 + 1]);
                *(float2*)(Cs + lr * CW + wn * 64 + nt * 8 + 2 * tig) = v;
            }
        }
    __syncthreads();

    if (tid < BM) {
        // Row-anchor: anchor m0+tid, candidates n0+c. 4 parallel chains (by quad).
        const int aid = s_idr[tid];
        const int4* idc4 = (const int4*)s_idc;
        float vmax[4] = {NEG_INF_F, NEG_INF_F, NEG_INF_F, NEG_INF_F};
        float vmin[4] = {POS_INF_F, POS_INF_F, POS_INF_F, POS_INF_F};
#pragma unroll
        for (int c16 = 0; c16 < 8; ++c16) {
#pragma unroll
            for (int q = 0; q < 4; ++q) {
                const int cb = c16 * 16 + q * 4;
                float4 v = *(const float4*)(Cs + tid * CW + cb);
                int4 id = idc4[cb >> 2];
                float s0 = (diag && cb + 0 == tid) ? 0.0f : v.x;
                float s1 = (diag && cb + 1 == tid) ? 0.0f : v.y;
                float s2 = (diag && cb + 2 == tid) ? 0.0f : v.z;
                float s3 = (diag && cb + 3 == tid) ? 0.0f : v.w;
                if (aid == id.x) vmin[q] = fminf(vmin[q], s0); else vmax[q] = fmaxf(vmax[q], s0);
                if (aid == id.y) vmin[q] = fminf(vmin[q], s1); else vmax[q] = fmaxf(vmax[q], s1);
                if (aid == id.z) vmin[q] = fminf(vmin[q], s2); else vmax[q] = fmaxf(vmax[q], s2);
                if (aid == id.w) vmin[q] = fminf(vmin[q], s3); else vmax[q] = fmaxf(vmax[q], s3);
            }
        }
        float fmax_ = fmaxf(fmaxf(vmax[0], vmax[1]), fmaxf(vmax[2], vmax[3]));
        float fmin_ = fminf(fminf(vmin[0], vmin[1]), fminf(vmin[2], vmin[3]));
        atomicMax(&g_max_enc[m0 + tid], enc_f(fmax_));
        atomicMin(&g_min_enc[m0 + tid], enc_f(fmin_));
    } else if (!diag) {
        // Col-anchor: anchor n0+c, candidates m0+r. 4 parallel chains (by r mod 4).
        const int c = tid - BM;
        const int aid = s_idc[c];
        const int4* idr4 = (const int4*)s_idr;
        float vmax[4] = {NEG_INF_F, NEG_INF_F, NEG_INF_F, NEG_INF_F};
        float vmin[4] = {POS_INF_F, POS_INF_F, POS_INF_F, POS_INF_F};
#pragma unroll
        for (int r4 = 0; r4 < 32; ++r4) {
            int4 id = idr4[r4];
            float s0 = Cs[(r4 * 4 + 0) * CW + c];
            float s1 = Cs[(r4 * 4 + 1) * CW + c];
            float s2 = Cs[(r4 * 4 + 2) * CW + c];
            float s3 = Cs[(r4 * 4 + 3) * CW + c];
            if (aid == id.x) vmin[0] = fminf(vmin[0], s0); else vmax[0] = fmaxf(vmax[0], s0);
            if (aid == id.y) vmin[1] = fminf(vmin[1], s1); else vmax[1] = fmaxf(vmax[1], s1);
            if (aid == id.z) vmin[2] = fminf(vmin[2], s2); else vmax[2] = fmaxf(vmax[2], s2);
            if (aid == id.w) vmin[3] = fminf(vmin[3], s3); else vmax[3] = fmaxf(vmax[3], s3);
        }
        float fmax_ = fmaxf(fmaxf(vmax[0], vmax[1]), fmaxf(vmax[2], vmax[3]));
        float fmin_ = fminf(fminf(vmin[0], vmin[1]), fminf(vmin[2], vmin[3]));
        atomicMax(&g_max_enc[n0 + c], enc_f(fmax_));
        atomicMin(&g_min_enc[n0 + c], enc_f(fmin_));
    }
}

// ---------------------------------------------------------------------------
// Kernel 3: deterministic scalar reduction of the hinge loss.
// ---------------------------------------------------------------------------
__global__ void finalize_kernel(float* __restrict__ out) {
    __shared__ float part[1024];
    float s = 0.0f;
    for (int i = threadIdx.x; i < B_ROWS; i += 1024) {
        s += fmaxf(MARGIN_F + dec_f(g_max_enc[i]) - dec_f(g_min_enc[i]), 0.0f);
    }
    part[threadIdx.x] = s;
    __syncthreads();
    for (int o = 512; o; o >>= 1) {
        if (threadIdx.x < o) part[threadIdx.x] += part[threadIdx.x + o];
        __syncthreads();
    }
    if (threadIdx.x == 0) out[0] = part[0];
}

extern "C" void kernel_launch(void* const* d_in, const int* in_sizes, int n_in,
                              void* d_out, int out_size) {
    const float* im  = (const float*)d_in[0];
    const void*  ids = d_in[1];

    static const int SMEM_BYTES = 2 * BM * SH * 2;   // 69632 B (Cs fits inside)
    cudaFuncSetAttribute(tile_kernel, cudaFuncAttributeMaxDynamicSharedMemorySize, SMEM_BYTES);

    convert_kernel<<<1024, 256>>>(im, ids);
    tile_kernel<<<NTILES, 256, SMEM_BYTES>>>();
    finalize_kernel<<<1, 1024>>>((float*)d_out);
}

// round 8
// speedup vs baseline: 1.0197x; 1.0197x over previous
#include <cuda_runtime.h>
#include <cuda_bf16.h>
#include <cstdint>

#define B_ROWS 8192
#define DIM    128
#define BM     128
#define SH     136            // halves per smem bf16 row (272 B): LDSM conflict-free
#define CW     132            // floats per smem score row (16B-aligned rows)
#define NBLK   64             // 8192/128 row blocks
#define NTILES 2080           // 64 diag + 2016 off-diag
#define NEG_INF_F (-1e30f)
#define POS_INF_F ( 1e30f)
#define MARGIN_F  0.2f

// ---------------- device-global state ----------------
__device__ unsigned       g_max_enc[B_ROWS];
__device__ unsigned       g_min_enc[B_ROWS];
__device__ __nv_bfloat16  g_im_bf16[B_ROWS * DIM];   // 2 MB, L2-resident
__device__ int            g_ids32[B_ROWS];
__device__ int            g_flags[NBLK];             // block-converted flags (reset each launch)
__device__ int            g_done;                    // completed-CTA counter (reset each launch)

__device__ __forceinline__ unsigned enc_f(float f) {
    unsigned u = __float_as_uint(f);
    return (u & 0x80000000u) ? ~u : (u | 0x80000000u);
}
__device__ __forceinline__ float dec_f(unsigned u) {
    return __uint_as_float((u & 0x80000000u) ? (u & 0x7FFFFFFFu) : ~u);
}
__device__ __forceinline__ uint32_t smem_u32(const void* p) {
    uint32_t a;
    asm("{ .reg .u64 t; cvta.to.shared.u64 t, %1; cvt.u32.u64 %0, t; }" : "=r"(a) : "l"(p));
    return a;
}
#define LDSM_X4(r0, r1, r2, r3, addr) \
    asm volatile("ldmatrix.sync.aligned.m8n8.x4.shared.b16 {%0,%1,%2,%3}, [%4];" \
                 : "=r"(r0), "=r"(r1), "=r"(r2), "=r"(r3) : "r"(addr))

// ---------------------------------------------------------------------------
// Single fused kernel.
// bid < 64: diagonal tile (bi=bj=bid) — converts its 128-row block fp32->bf16
//   (into smem AND g_im_bf16), converts its ids, inits its reduction rows,
//   sets flags[bid]. ids dtype detected from SAFE low words [1..129] only
//   (in bounds for int32 AND int64 serializations; identical in every CTA).
// bid >= 64: off-diagonal tile — spins on flags[bi], flags[bj], then stages
//   bf16 from g_im_bf16 (L2).
// All tiles: bf16 m16n8k16 mainloop (ldmatrix), smem-transpose epilogue,
// encoded global atomics. Last CTA computes the scalar loss + resets state.
// ---------------------------------------------------------------------------
__global__ void __launch_bounds__(256, 2)
tile_kernel(const float* __restrict__ im, const void* __restrict__ ids,
            float* __restrict__ out) {
    // ---- block-id -> (bi, bj) ----
    int bi, bj;
    {
        const int bid = blockIdx.x;
        if (bid < NBLK) { bi = bid; bj = bid; }
        else {
            int k = bid - NBLK;                     // 0..2015 strict-upper pairs
            int b = (int)(63.5f - sqrtf(4032.25f - 2.0f * (float)k));
            if (b < 0) b = 0;
            while (63 * b - b * (b - 1) / 2 > k) --b;
            while (63 * (b + 1) - (b + 1) * b / 2 <= k) ++b;
            bi = b;
            bj = b + 1 + (k - (63 * b - b * (b - 1) / 2));
        }
    }
    const bool diag = (bi == bj);
    const int m0 = bi * BM, n0 = bj * BM;

    extern __shared__ char smem[];
    unsigned short* As = (unsigned short*)smem;          // [BM][SH]
    unsigned short* Bs = As + BM * SH;                   // [BM][SH]
    float*          Cs = (float*)smem;                   // [BM][CW], aliases A/B
    __shared__ int s_idr[BM], s_idc[BM];
    __shared__ int s_is64;
    __shared__ bool s_last;

    const int tid = threadIdx.x;

    if (diag) {
        // ---- converter path ----
        if (tid < 32) {
            // SAFE detection: odd words 1..129 only (first 64 int64 entries).
            // int64 LE ids in [0,512) -> all zero; int32 random -> nonzero.
            const unsigned* w = (const unsigned*)ids;
            unsigned v = w[2 * tid + 1] | w[2 * tid + 65];
            unsigned any = __ballot_sync(0xffffffffu, v != 0u);
            if (tid == 0) s_is64 = (any == 0u) ? 1 : 0;
        }
        __syncthreads();
        if (tid < BM) {
            int idv = s_is64 ? (int)((const long long*)ids)[m0 + tid]
                             : ((const int*)ids)[m0 + tid];
            g_ids32[m0 + tid] = idv;
            s_idr[tid] = idv;
            s_idc[tid] = idv;
            g_max_enc[m0 + tid] = enc_f(NEG_INF_F);
            g_min_enc[m0 + tid] = enc_f(POS_INF_F);
        }
#pragma unroll
        for (int it = 0; it < 16; ++it) {
            int idx = it * 256 + tid;            // 4096 float4 chunks (128 x 32)
            int row = idx >> 5, c4 = idx & 31;
            float4 v = *(const float4*)(im + (size_t)(m0 + row) * DIM + c4 * 4);
            __nv_bfloat162 p0 = __floats2bfloat162_rn(v.x, v.y);
            __nv_bfloat162 p1 = __floats2bfloat162_rn(v.z, v.w);
            uint2 pk = make_uint2(*(unsigned*)&p0, *(unsigned*)&p1);
            *(uint2*)(As + row * SH + c4 * 4) = pk;
            *(uint2*)(g_im_bf16 + (size_t)(m0 + row) * DIM + c4 * 4) = pk;
        }
        __threadfence();
        __syncthreads();
        if (tid == 0) atomicExch(&g_flags[bi], 1);
    } else {
        // ---- waiter path: spin on both source blocks, then stage from bf16 ----
        if (tid == 0) {
            while (atomicAdd(&g_flags[bi], 0) == 0) __nanosleep(64);
            while (atomicAdd(&g_flags[bj], 0) == 0) __nanosleep(64);
            __threadfence();
        }
        __syncthreads();
        __threadfence();
        if (tid < BM) {
            s_idr[tid] = g_ids32[m0 + tid];
            s_idc[tid] = g_ids32[n0 + tid];
        }
#pragma unroll
        for (int it = 0; it < 8; ++it) {
            int idx = it * 256 + tid;
            int row = idx >> 4, q = idx & 15;    // q: 16B chunk in 256B row
            *(uint4*)(As + row * SH + q * 8) =
                *(const uint4*)(g_im_bf16 + (size_t)(m0 + row) * DIM + q * 8);
            *(uint4*)(Bs + row * SH + q * 8) =
                *(const uint4*)(g_im_bf16 + (size_t)(n0 + row) * DIM + q * 8);
        }
        __syncthreads();
    }

    const int warp = tid >> 5, lane = tid & 31;
    const int wm = warp >> 1, wn = warp & 1;     // warp tile origin (wm*32, wn*64)
    const int g = lane >> 2, tig = lane & 3;
    const int grp = lane >> 3, rin = lane & 7;

    const unsigned short* BsEff = diag ? As : Bs;    // diagonal: B tile == A tile
    const uint32_t As32 = smem_u32(As), Bs32 = smem_u32(BsEff);
    uint32_t aaddr[2], baddr[4];
#pragma unroll
    for (int mt = 0; mt < 2; ++mt)
        aaddr[mt] = As32 + 2 * ((wm * 32 + mt * 16 + (grp & 1) * 8 + rin) * SH + (grp >> 1) * 8);
#pragma unroll
    for (int q = 0; q < 4; ++q)
        baddr[q] = Bs32 + 2 * ((wn * 64 + 16 * q + (grp >> 1) * 8 + rin) * SH + (grp & 1) * 8);

    float acc[2][8][4];
#pragma unroll
    for (int mt = 0; mt < 2; ++mt)
#pragma unroll
        for (int nt = 0; nt < 8; ++nt)
#pragma unroll
            for (int r = 0; r < 4; ++r) acc[mt][nt][r] = 0.0f;

#pragma unroll
    for (int ks = 0; ks < 8; ++ks) {
        const uint32_t koff = ks * 32;           // 16 halves = 32 bytes
        unsigned a[2][4], b[8][2];
#pragma unroll
        for (int mt = 0; mt < 2; ++mt)
            LDSM_X4(a[mt][0], a[mt][1], a[mt][2], a[mt][3], aaddr[mt] + koff);
#pragma unroll
        for (int q = 0; q < 4; ++q)
            LDSM_X4(b[2 * q][0], b[2 * q][1], b[2 * q + 1][0], b[2 * q + 1][1], baddr[q] + koff);
#pragma unroll
        for (int mt = 0; mt < 2; ++mt)
#pragma unroll
            for (int nt = 0; nt < 8; ++nt) {
                asm volatile(
                    "mma.sync.aligned.m16n8k16.row.col.f32.bf16.bf16.f32 "
                    "{%0,%1,%2,%3}, {%4,%5,%6,%7}, {%8,%9}, {%0,%1,%2,%3};"
                    : "+f"(acc[mt][nt][0]), "+f"(acc[mt][nt][1]),
                      "+f"(acc[mt][nt][2]), "+f"(acc[mt][nt][3])
                    : "r"(a[mt][0]), "r"(a[mt][1]), "r"(a[mt][2]), "r"(a[mt][3]),
                      "r"(b[nt][0]), "r"(b[nt][1]));
            }
    }
    __syncthreads();   // done reading As/Bs; Cs may overwrite

    // Scatter acc to Cs: row = wm*32+mt*16+g+half*8, cols wn*64+nt*8+2*tig+{0,1}
#pragma unroll
    for (int mt = 0; mt < 2; ++mt)
#pragma unroll
        for (int half = 0; half < 2; ++half) {
            const int lr = wm * 32 + mt * 16 + g + half * 8;
#pragma unroll
            for (int nt = 0; nt < 8; ++nt) {
                float2 v = make_float2(acc[mt][nt][half * 2], acc[mt][nt][half * 2 + 1]);
                *(float2*)(Cs + lr * CW + wn * 64 + nt * 8 + 2 * tig) = v;
            }
        }
    __syncthreads();

    if (tid < BM) {
        // Row-anchor: anchor m0+tid, candidates n0+c  (exact R5 epilogue)
        const int aid = s_idr[tid];
        float vmax = NEG_INF_F, vmin = POS_INF_F;
#pragma unroll 8
        for (int c4 = 0; c4 < 32; ++c4) {
            float4 v = *(const float4*)(Cs + tid * CW + c4 * 4);
            float sv[4] = {v.x, v.y, v.z, v.w};
#pragma unroll
            for (int j = 0; j < 4; ++j) {
                int c = c4 * 4 + j;
                float s = (diag && c == tid) ? 0.0f : sv[j];
                if (aid == s_idc[c]) vmin = fminf(vmin, s);
                else                 vmax = fmaxf(vmax, s);
            }
        }
        atomicMax(&g_max_enc[m0 + tid], enc_f(vmax));
        atomicMin(&g_min_enc[m0 + tid], enc_f(vmin));
    } else if (!diag) {
        // Col-anchor: anchor n0+c, candidates m0+r (transpose view)
        const int c = tid - BM;
        const int aid = s_idc[c];
        float vmax = NEG_INF_F, vmin = POS_INF_F;
#pragma unroll 8
        for (int r = 0; r < BM; ++r) {
            float s = Cs[r * CW + c];
            if (aid == s_idr[r]) vmin = fminf(vmin, s);
            else                 vmax = fmaxf(vmax, s);
        }
        atomicMax(&g_max_enc[n0 + c], enc_f(vmax));
        atomicMin(&g_min_enc[n0 + c], enc_f(vmin));
    }

    // ---- fused finalize: last CTA reduces the loss and resets launch state ----
    __threadfence();
    __syncthreads();
    if (tid == 0) s_last = (atomicAdd(&g_done, 1) == NTILES - 1);
    __syncthreads();
    if (s_last) {
        __threadfence();
        float s = 0.0f;
        for (int i = tid; i < B_ROWS; i += 256)
            s += fmaxf(MARGIN_F + dec_f(g_max_enc[i]) - dec_f(g_min_enc[i]), 0.0f);
        Cs[tid] = s;
        __syncthreads();
        for (int o = 128; o; o >>= 1) {
            if (tid < o) Cs[tid] += Cs[tid + o];
            __syncthreads();
        }
        if (tid == 0) {
            out[0] = Cs[0];
            g_done = 0;                              // reset for next graph replay
            for (int f = 0; f < NBLK; ++f) g_flags[f] = 0;
        }
    }
}

extern "C" void kernel_launch(void* const* d_in, const int* in_sizes, int n_in,
                              void* d_out, int out_size) {
    const float* im  = (const float*)d_in[0];
    const void*  ids = d_in[1];

    static const int SMEM_BYTES = 2 * BM * SH * 2;   // 69632 B (Cs fits inside)
    cudaFuncSetAttribute(tile_kernel, cudaFuncAttributeMaxDynamicSharedMemorySize, SMEM_BYTES);

    tile_kernel<<<NTILES, 256, SMEM_BYTES>>>(im, ids, (float*)d_out);
}

// round 9
// speedup vs baseline: 1.4034x; 1.3763x over previous
#include <cuda_runtime.h>
#include <cuda_bf16.h>
#include <cstdint>

#define B_ROWS 8192
#define DIM    128
#define BM     128
#define SH     136            // halves per smem bf16 row (272 B): LDSM conflict-free
#define NBLK   64
#define NTILES 2080           // 64 diag + 2016 off-diag
#define NEG_INF_F (-1e30f)
#define POS_INF_F ( 1e30f)
#define MARGIN_F  0.2f

// ---------------- device-global state ----------------
__device__ unsigned       g_max_enc[B_ROWS];
__device__ unsigned       g_min_enc[B_ROWS];
__device__ __nv_bfloat16  g_im_bf16[B_ROWS * DIM];   // 2 MB, L2-resident
__device__ int            g_ids32[B_ROWS];

__device__ __forceinline__ unsigned enc_f(float f) {
    unsigned u = __float_as_uint(f);
    return (u & 0x80000000u) ? ~u : (u | 0x80000000u);
}
__device__ __forceinline__ float dec_f(unsigned u) {
    return __uint_as_float((u & 0x80000000u) ? (u & 0x7FFFFFFFu) : ~u);
}
__device__ __forceinline__ uint32_t smem_u32(const void* p) {
    uint32_t a;
    asm("{ .reg .u64 t; cvta.to.shared.u64 t, %1; cvt.u32.u64 %0, t; }" : "=r"(a) : "l"(p));
    return a;
}
#define LDSM_X4(r0, r1, r2, r3, addr) \
    asm volatile("ldmatrix.sync.aligned.m8n8.x4.shared.b16 {%0,%1,%2,%3}, [%4];" \
                 : "=r"(r0), "=r"(r1), "=r"(r2), "=r"(r3) : "r"(addr))

// ---------------------------------------------------------------------------
// Kernel 1: convert im -> bf16, ids -> int32, clear reduction arrays.
// ids dtype: SAFE detection from odd words 1..129 (in bounds for both dtypes).
// ---------------------------------------------------------------------------
__global__ void convert_kernel(const float* __restrict__ im, const void* __restrict__ ids) {
    __shared__ int s_is64;
    const int tid = blockIdx.x * blockDim.x + threadIdx.x;   // 1024*256

    if (blockIdx.x < 32) {
        if (threadIdx.x < 32) {
            const unsigned* w = (const unsigned*)ids;
            unsigned v = w[2 * threadIdx.x + 1] | w[2 * threadIdx.x + 65];
            unsigned any = __ballot_sync(0xffffffffu, v != 0u);
            if (threadIdx.x == 0) s_is64 = (any == 0u) ? 1 : 0;
        }
        __syncthreads();
        g_max_enc[tid] = enc_f(NEG_INF_F);
        g_min_enc[tid] = enc_f(POS_INF_F);
        g_ids32[tid] = s_is64 ? (int)((const long long*)ids)[tid]
                              : ((const int*)ids)[tid];
    }
    float4 v = ((const float4*)im)[tid];
    __nv_bfloat162* dst = (__nv_bfloat162*)g_im_bf16 + (size_t)tid * 2;
    dst[0] = __floats2bfloat162_rn(v.x, v.y);
    dst[1] = __floats2bfloat162_rn(v.z, v.w);
}

// ---------------------------------------------------------------------------
// Kernel 2: symmetric bf16 mma.sync tile, register-pooled masked reduction.
// 8 warps (4m x 2n), warp tile 32x64, mma m16n8k16 fed by ldmatrix.x4.
// Epilogue: one scan of acc classifies each element into per-row and
// per-col (min,max) pools in registers; only 40KB of partials hit smem.
// ---------------------------------------------------------------------------
#define SROW_OFF (2 * BM * SH * 2)                 // 69632
#define SCOL_OFF (SROW_OFF + 8 * BM * 8)           // + 8KB
#define SMEM_TOTAL (SCOL_OFF + 32 * BM * 8)        // + 32KB = 110592

__global__ void __launch_bounds__(256, 2)
tile_kernel(void) {
    // ---- block-id -> (bi, bj): first 64 = diagonal, rest strict-upper ----
    int bi, bj;
    {
        const int bid = blockIdx.x;
        if (bid < NBLK) { bi = bid; bj = bid; }
        else {
            int k = bid - NBLK;
            int b = (int)(63.5f - sqrtf(4032.25f - 2.0f * (float)k));
            if (b < 0) b = 0;
            while (63 * b - b * (b - 1) / 2 > k) --b;
            while (63 * (b + 1) - (b + 1) * b / 2 <= k) ++b;
            bi = b;
            bj = b + 1 + (k - (63 * b - b * (b - 1) / 2));
        }
    }
    const bool diag = (bi == bj);
    const int m0 = bi * BM, n0 = bj * BM;

    extern __shared__ char smem[];
    unsigned short* As = (unsigned short*)smem;          // [BM][SH]
    unsigned short* Bs = As + BM * SH;                   // [BM][SH]
    float2* sRow = (float2*)(smem + SROW_OFF);           // [8][BM]
    float2* sCol = (float2*)(smem + SCOL_OFF);           // [32][BM]
    __shared__ int s_idr[BM], s_idc[BM];

    const int tid = threadIdx.x;
    if (tid < BM) {
        s_idr[tid] = g_ids32[m0 + tid];
        s_idc[tid] = g_ids32[n0 + tid];
    }

    // Stage bf16 tiles: 2048 x 16B each.
#pragma unroll
    for (int it = 0; it < 8; ++it) {
        int idx = it * 256 + tid;
        int row = idx >> 4, q = idx & 15;
        *(uint4*)(As + row * SH + q * 8) =
            *(const uint4*)(g_im_bf16 + (size_t)(m0 + row) * DIM + q * 8);
        *(uint4*)(Bs + row * SH + q * 8) =
            *(const uint4*)(g_im_bf16 + (size_t)(n0 + row) * DIM + q * 8);
    }
    __syncthreads();

    const int warp = tid >> 5, lane = tid & 31;
    const int wm = warp >> 1, wn = warp & 1;     // warp tile origin (wm*32, wn*64)
    const int g = lane >> 2, tig = lane & 3;
    const int grp = lane >> 3, rin = lane & 7;

    const uint32_t As32 = smem_u32(As), Bs32 = smem_u32(Bs);
    uint32_t aaddr[2], baddr[4];
#pragma unroll
    for (int mt = 0; mt < 2; ++mt)
        aaddr[mt] = As32 + 2 * ((wm * 32 + mt * 16 + (grp & 1) * 8 + rin) * SH + (grp >> 1) * 8);
#pragma unroll
    for (int q = 0; q < 4; ++q)
        baddr[q] = Bs32 + 2 * ((wn * 64 + 16 * q + (grp >> 1) * 8 + rin) * SH + (grp & 1) * 8);

    float acc[2][8][4];
#pragma unroll
    for (int mt = 0; mt < 2; ++mt)
#pragma unroll
        for (int nt = 0; nt < 8; ++nt)
#pragma unroll
            for (int r = 0; r < 4; ++r) acc[mt][nt][r] = 0.0f;

#pragma unroll
    for (int ks = 0; ks < 8; ++ks) {
        const uint32_t koff = ks * 32;
        unsigned a[2][4], b[8][2];
#pragma unroll
        for (int mt = 0; mt < 2; ++mt)
            LDSM_X4(a[mt][0], a[mt][1], a[mt][2], a[mt][3], aaddr[mt] + koff);
#pragma unroll
        for (int q = 0; q < 4; ++q)
            LDSM_X4(b[2 * q][0], b[2 * q][1], b[2 * q + 1][0], b[2 * q + 1][1], baddr[q] + koff);
#pragma unroll
        for (int mt = 0; mt < 2; ++mt)
#pragma unroll
            for (int nt = 0; nt < 8; ++nt) {
                asm volatile(
                    "mma.sync.aligned.m16n8k16.row.col.f32.bf16.bf16.f32 "
                    "{%0,%1,%2,%3}, {%4,%5,%6,%7}, {%8,%9}, {%0,%1,%2,%3};"
                    : "+f"(acc[mt][nt][0]), "+f"(acc[mt][nt][1]),
                      "+f"(acc[mt][nt][2]), "+f"(acc[mt][nt][3])
                    : "r"(a[mt][0]), "r"(a[mt][1]), "r"(a[mt][2]), "r"(a[mt][3]),
                      "r"(b[nt][0]), "r"(b[nt][1]));
            }
    }
    // No barrier: partial arrays don't alias As/Bs.

    // ---- register-pooled epilogue ----
    // rows: lr(mt,half) = wm*32 + mt*16 + g + half*8 ; cols: lc(nt,e) = wn*64 + nt*8 + 2*tig + e
    int rids[4];
#pragma unroll
    for (int mt = 0; mt < 2; ++mt)
#pragma unroll
        for (int half = 0; half < 2; ++half)
            rids[mt * 2 + half] = s_idr[wm * 32 + mt * 16 + g + half * 8];

    float rmin[4] = {POS_INF_F, POS_INF_F, POS_INF_F, POS_INF_F};
    float rmax[4] = {NEG_INF_F, NEG_INF_F, NEG_INF_F, NEG_INF_F};

#pragma unroll
    for (int ph = 0; ph < 2; ++ph) {                 // two phases of 4 nt (8 cols)
        float cmin[8], cmax[8];
        int cids[8];
#pragma unroll
        for (int i = 0; i < 8; ++i) {
            cmin[i] = POS_INF_F; cmax[i] = NEG_INF_F;
            int nt = ph * 4 + (i >> 1);
            cids[i] = s_idc[wn * 64 + nt * 8 + 2 * tig + (i & 1)];
        }
#pragma unroll
        for (int i = 0; i < 8; ++i) {
            const int nt = ph * 4 + (i >> 1), e = i & 1;
            const int lc = wn * 64 + nt * 8 + 2 * tig + e;
            const int cid = cids[i];
#pragma unroll
            for (int mt = 0; mt < 2; ++mt)
#pragma unroll
                for (int half = 0; half < 2; ++half) {
                    const int ri = mt * 2 + half;
                    float s = acc[mt][nt][half * 2 + e];
                    if (diag && (wm * 32 + mt * 16 + g + half * 8) == lc) s = 0.0f;
                    if (rids[ri] == cid) {
                        rmin[ri] = fminf(rmin[ri], s);
                        cmin[i]  = fminf(cmin[i], s);
                    } else {
                        rmax[ri] = fmaxf(rmax[ri], s);
                        cmax[i]  = fmaxf(cmax[i], s);
                    }
                }
        }
        if (!diag) {
            const int slot = wm * 8 + g;             // 0..31
#pragma unroll
            for (int i = 0; i < 8; ++i) {
                const int nt = ph * 4 + (i >> 1);
                const int lc = wn * 64 + nt * 8 + 2 * tig + (i & 1);
                sCol[slot * BM + lc] = make_float2(cmin[i], cmax[i]);
            }
        }
    }
    {
        const int slot = wn * 4 + tig;               // 0..7
#pragma unroll
        for (int ri = 0; ri < 4; ++ri) {
            const int lr = wm * 32 + (ri >> 1) * 16 + g + (ri & 1) * 8;
            sRow[slot * BM + lr] = make_float2(rmin[ri], rmax[ri]);
        }
    }
    __syncthreads();

    if (tid < BM) {
        float vmin = POS_INF_F, vmax = NEG_INF_F;
#pragma unroll
        for (int s = 0; s < 8; ++s) {
            float2 p = sRow[s * BM + tid];
            vmin = fminf(vmin, p.x);
            vmax = fmaxf(vmax, p.y);
        }
        atomicMax(&g_max_enc[m0 + tid], enc_f(vmax));
        atomicMin(&g_min_enc[m0 + tid], enc_f(vmin));
    } else if (!diag) {
        const int c = tid - BM;
        float vmin = POS_INF_F, vmax = NEG_INF_F;
#pragma unroll
        for (int s = 0; s < 32; ++s) {
            float2 p = sCol[s * BM + c];
            vmin = fminf(vmin, p.x);
            vmax = fmaxf(vmax, p.y);
        }
        atomicMax(&g_max_enc[n0 + c], enc_f(vmax));
        atomicMin(&g_min_enc[n0 + c], enc_f(vmin));
    }
}

// ---------------------------------------------------------------------------
// Kernel 3: deterministic scalar reduction of the hinge loss.
// ---------------------------------------------------------------------------
__global__ void finalize_kernel(float* __restrict__ out) {
    __shared__ float part[1024];
    float s = 0.0f;
    for (int i = threadIdx.x; i < B_ROWS; i += 1024) {
        s += fmaxf(MARGIN_F + dec_f(g_max_enc[i]) - dec_f(g_min_enc[i]), 0.0f);
    }
    part[threadIdx.x] = s;
    __syncthreads();
    for (int o = 512; o; o >>= 1) {
        if (threadIdx.x < o) part[threadIdx.x] += part[threadIdx.x + o];
        __syncthreads();
    }
    if (threadIdx.x == 0) out[0] = part[0];
}

extern "C" void kernel_launch(void* const* d_in, const int* in_sizes, int n_in,
                              void* d_out, int out_size) {
    const float* im  = (const float*)d_in[0];
    const void*  ids = d_in[1];

    cudaFuncSetAttribute(tile_kernel, cudaFuncAttributeMaxDynamicSharedMemorySize, SMEM_TOTAL);

    convert_kernel<<<1024, 256>>>(im, ids);
    tile_kernel<<<NTILES, 256, SMEM_TOTAL>>>();
    finalize_kernel<<<1, 1024>>>((float*)d_out);
}